// round 9
// baseline (speedup 1.0000x reference)
#include <cuda_runtime.h>

// B=32, L=1024, D=64.
// Algebraic collapse (verified R1-R8, rel_err ~1.4e-7):
//   out[b,0,:] = sum_l x[b,l,:] / 1024 ;  out[b,1:,:] = 0.
//   W1,b1,W2,b2,timestamp are dead inputs.
//
// R9 = R6 (best: role-partitioned SMs, grid 148 x 1024, 1 CTA/SM) with the
// read-block exit tail cut: single-warp batched smem reduce (8 pipelined LDS
// + tree + 2 shuffles, ~150cyc) instead of 8 threads x 31 serial adds (~600).
//   bids [0,64):   READ blocks. (batch b, 128B column half h), exclusive
//                  owner of out[b,0, h*32 : h*32+32) floats.
//   bids [64,148): ZERO blocks. grid-stride zeros over rows 1..1023.

#define RED_BLOCKS   64
#define TOTAL_BLOCKS 148
#define ZERO_BLOCKS  (TOTAL_BLOCKS - RED_BLOCKS)
#define NTHREADS     1024

#define F4_PER_BATCH 16384u   // 1024 rows * 16 float4
#define F4_PER_ROW   16u
#define N_F4_TOTAL   (32u * F4_PER_BATCH)

__device__ __forceinline__ void f4add(float4& a, const float4& b) {
    a.x += b.x; a.y += b.y; a.z += b.z; a.w += b.w;
}

__device__ __forceinline__ float4 f4shfl_down(float4 v, int delta) {
    v.x = __shfl_down_sync(0xffffffffu, v.x, delta);
    v.y = __shfl_down_sync(0xffffffffu, v.y, delta);
    v.z = __shfl_down_sync(0xffffffffu, v.z, delta);
    v.w = __shfl_down_sync(0xffffffffu, v.w, delta);
    return v;
}

__global__ void __launch_bounds__(NTHREADS, 1) um_fused_kernel(
    const float4* __restrict__ x4, float4* __restrict__ out4)
{
    const int bid = blockIdx.x;
    const int tid = threadIdx.x;

    if (bid < RED_BLOCKS) {
        // ---- READ block: (b, h) owns the 128B slice h of row 0 -----------
        const int b  = bid >> 1;
        const int h  = bid & 1;
        const int c  = tid & 7;        // float4 column within 128B slice
        const int lg = tid >> 3;       // 0..127: row group

        const float4* base = x4 + (size_t)b * F4_PER_BATCH
                                + (size_t)lg * F4_PER_ROW + h * 8 + c;

        // 8 independent LDG.128 from one base + immediate offsets (MLP=8)
        float4 v[8];
        #pragma unroll
        for (int j = 0; j < 8; ++j)
            v[j] = base[(size_t)j * 128u * F4_PER_ROW];   // +128 rows each

        float4 a0 = v[0], a1 = v[1], a2 = v[2], a3 = v[3];
        f4add(a0, v[4]); f4add(a1, v[5]); f4add(a2, v[6]); f4add(a3, v[7]);
        f4add(a0, a1); f4add(a2, a3); f4add(a0, a2);

        // warp reduce: lanes sharing (lane & 7) share a column
        f4add(a0, f4shfl_down(a0, 16));
        f4add(a0, f4shfl_down(a0, 8));

        __shared__ float4 sm[32][8];   // [warp][col]
        const int lane = tid & 31;
        const int wid  = tid >> 5;
        if (lane < 8) sm[wid][lane] = a0;
        __syncthreads();

        // single-warp batched final reduce:
        // lane = (g, cc): g = lane>>3 owns warps [g*8, g*8+8), cc = lane&7.
        if (wid == 0) {
            const int cc = lane & 7;
            const int g  = lane >> 3;
            float4 u[8];
            #pragma unroll
            for (int k = 0; k < 8; ++k)      // 8 pipelined LDS.128
                u[k] = sm[g * 8 + k][cc];
            f4add(u[0], u[1]); f4add(u[2], u[3]);
            f4add(u[4], u[5]); f4add(u[6], u[7]);
            f4add(u[0], u[2]); f4add(u[4], u[6]); f4add(u[0], u[4]);

            float4 t = u[0];
            f4add(t, f4shfl_down(t, 16));    // combine g=0/2, 1/3
            f4add(t, f4shfl_down(t, 8));     // combine g=0/1

            if (lane < 8) {
                const float inv = 1.0f / 1024.0f;
                t.x *= inv; t.y *= inv; t.z *= inv; t.w *= inv;
                out4[(size_t)b * F4_PER_BATCH + h * 8 + lane] = t;
            }
        }
    } else {
        // ---- ZERO block: everything except row 0 of each batch -----------
        const unsigned zid  = (unsigned)(bid - RED_BLOCKS);
        const unsigned step = ZERO_BLOCKS * (unsigned)NTHREADS;
        const float4 z = make_float4(0.f, 0.f, 0.f, 0.f);
        for (unsigned i = zid * (unsigned)NTHREADS + (unsigned)tid;
             i < N_F4_TOTAL; i += step) {
            if ((i & (F4_PER_BATCH - 1u)) >= F4_PER_ROW)   // skip row 0
                out4[i] = z;
        }
    }
}

extern "C" void kernel_launch(void* const* d_in, const int* in_sizes, int n_in,
                              void* d_out, int out_size) {
    const float4* x4 = (const float4*)d_in[0];   // user_embedding [32,1024,64]
    float4* out4 = (float4*)d_out;               // [32,1024,64]
    um_fused_kernel<<<TOTAL_BLOCKS, NTHREADS>>>(x4, out4);
}

// round 10
// speedup vs baseline: 1.0463x; 1.0463x over previous
#include <cuda_runtime.h>

// B=32, L=1024, D=64.
// Algebraic collapse (verified R1-R9, rel_err ~1.4e-7):
//   out[b,0,:] = sum_l x[b,l,:] / 1024 ;  out[b,1:,:] = 0.
//   W1,b1,W2,b2,timestamp are dead inputs.
//
// R10 = R6 structure (role-partitioned SMs, grid 148 x 1024, 1 CTA/SM) with
// 256-bit global memory ops (sm_100+ ld/st.global.v8.b32) on BOTH streams:
// halves LDG/STG instruction count and L1tex wavefronts.
//   bids [0,64):   READ blocks. (batch b, 128B column half h). Thread owns a
//                  32B chunk of the slice, 4 batched LDG.256 (rows lg,
//                  lg+256, lg+512, lg+768). Exclusive writer of
//                  out[b,0, h*32 : h*32+32).
//   bids [64,148): ZERO blocks. grid-stride STG.256 zeros over rows 1..1023.

#define RED_BLOCKS   64
#define TOTAL_BLOCKS 148
#define ZERO_BLOCKS  (TOTAL_BLOCKS - RED_BLOCKS)
#define NTHREADS     1024

#define FLOATS_PER_BATCH 65536u   // 1024 rows * 64
#define F8_PER_BATCH     8192u    // 32B chunks per batch
#define F8_PER_ROW       8u
#define N_F8_TOTAL       (32u * F8_PER_BATCH)   // 262144

struct __align__(32) f8 { float a[8]; };

__device__ __forceinline__ void ldg256(f8& r, const float* p) {
    unsigned u0,u1,u2,u3,u4,u5,u6,u7;
    asm volatile("ld.global.v8.b32 {%0,%1,%2,%3,%4,%5,%6,%7}, [%8];"
        : "=r"(u0),"=r"(u1),"=r"(u2),"=r"(u3),
          "=r"(u4),"=r"(u5),"=r"(u6),"=r"(u7)
        : "l"(p));
    r.a[0]=__uint_as_float(u0); r.a[1]=__uint_as_float(u1);
    r.a[2]=__uint_as_float(u2); r.a[3]=__uint_as_float(u3);
    r.a[4]=__uint_as_float(u4); r.a[5]=__uint_as_float(u5);
    r.a[6]=__uint_as_float(u6); r.a[7]=__uint_as_float(u7);
}

__device__ __forceinline__ void stg256(float* p, const f8& v) {
    asm volatile("st.global.v8.b32 [%0], {%1,%2,%3,%4,%5,%6,%7,%8};"
        :: "l"(p),
           "r"(__float_as_uint(v.a[0])), "r"(__float_as_uint(v.a[1])),
           "r"(__float_as_uint(v.a[2])), "r"(__float_as_uint(v.a[3])),
           "r"(__float_as_uint(v.a[4])), "r"(__float_as_uint(v.a[5])),
           "r"(__float_as_uint(v.a[6])), "r"(__float_as_uint(v.a[7]))
        : "memory");
}

__device__ __forceinline__ void stg256_zero(float* p) {
    asm volatile("st.global.v8.b32 [%0], {%1,%1,%1,%1,%1,%1,%1,%1};"
        :: "l"(p), "r"(0u) : "memory");
}

__global__ void __launch_bounds__(NTHREADS, 1) um_fused_kernel(
    const float* __restrict__ x, float* __restrict__ out)
{
    const int bid = blockIdx.x;
    const int tid = threadIdx.x;

    if (bid < RED_BLOCKS) {
        // ---- READ block: (b, h) owns the 128B slice h of row 0 -----------
        const int b  = bid >> 1;
        const int h  = bid & 1;
        const int c  = tid & 3;        // 32B chunk within the 128B slice
        const int lg = tid >> 2;       // 0..255: row group

        const float* base = x + (size_t)b * FLOATS_PER_BATCH
                              + (size_t)lg * 64u + h * 32 + c * 8;

        // 4 batched LDG.256 (MLP=4 x 32B), rows lg + {0,256,512,768}
        f8 v0, v1, v2, v3;
        ldg256(v0, base);
        ldg256(v1, base + 256u * 64u);
        ldg256(v2, base + 512u * 64u);
        ldg256(v3, base + 768u * 64u);

        f8 s;
        #pragma unroll
        for (int k = 0; k < 8; ++k)
            s.a[k] = (v0.a[k] + v1.a[k]) + (v2.a[k] + v3.a[k]);

        // warp reduce: lanes sharing (lane & 3) share a chunk
        #pragma unroll
        for (int d = 16; d >= 4; d >>= 1)
            #pragma unroll
            for (int k = 0; k < 8; ++k)
                s.a[k] += __shfl_down_sync(0xffffffffu, s.a[k], d);

        __shared__ float sm[32][4][8];   // [warp][chunk][elem]
        const int lane = tid & 31;
        const int wid  = tid >> 5;
        if (lane < 4) {
            #pragma unroll
            for (int k = 0; k < 8; ++k) sm[wid][lane][k] = s.a[k];
        }
        __syncthreads();

        // single-warp final reduce: lane = (g, cc), g owns warps g*4..g*4+3
        if (wid == 0) {
            const int cc = lane & 3;
            const int g  = lane >> 2;    // 0..7
            float t[8];
            #pragma unroll
            for (int k = 0; k < 8; ++k)
                t[k] = (sm[g*4+0][cc][k] + sm[g*4+1][cc][k])
                     + (sm[g*4+2][cc][k] + sm[g*4+3][cc][k]);
            #pragma unroll
            for (int d = 16; d >= 4; d >>= 1)
                #pragma unroll
                for (int k = 0; k < 8; ++k)
                    t[k] += __shfl_down_sync(0xffffffffu, t[k], d);
            if (lane < 4) {
                f8 o;
                const float inv = 1.0f / 1024.0f;
                #pragma unroll
                for (int k = 0; k < 8; ++k) o.a[k] = t[k] * inv;
                stg256(out + (size_t)b * FLOATS_PER_BATCH + h * 32 + lane * 8, o);
            }
        }
    } else {
        // ---- ZERO block: everything except row 0 of each batch -----------
        const unsigned zid  = (unsigned)(bid - RED_BLOCKS);
        const unsigned step = ZERO_BLOCKS * (unsigned)NTHREADS;
        for (unsigned i = zid * (unsigned)NTHREADS + (unsigned)tid;
             i < N_F8_TOTAL; i += step) {
            if ((i & (F8_PER_BATCH - 1u)) >= F8_PER_ROW)   // skip row 0
                stg256_zero(out + (size_t)i * 8u);
        }
    }
}

extern "C" void kernel_launch(void* const* d_in, const int* in_sizes, int n_in,
                              void* d_out, int out_size) {
    const float* x = (const float*)d_in[0];   // user_embedding [32,1024,64]
    float* out = (float*)d_out;               // [32,1024,64]
    um_fused_kernel<<<TOTAL_BLOCKS, NTHREADS>>>(x, out);
}

// round 11
// speedup vs baseline: 1.0918x; 1.0435x over previous
#include <cuda_runtime.h>

// B=32, L=1024, D=64.
// Algebraic collapse (verified R1-R9, rel_err ~1.4e-7):
//   out[b,0,:] = sum_l x[b,l,:] / 1024 ;  out[b,1:,:] = 0.
//   W1,b1,W2,b2,timestamp are dead inputs.
//
// R10 = R6 structure (role-partitioned SMs, grid 148 x 1024, 1 CTA/SM) with
// 256-bit global memory ops (sm_100+ ld/st.global.v8.b32) on BOTH streams:
// halves LDG/STG instruction count and L1tex wavefronts.
//   bids [0,64):   READ blocks. (batch b, 128B column half h). Thread owns a
//                  32B chunk of the slice, 4 batched LDG.256 (rows lg,
//                  lg+256, lg+512, lg+768). Exclusive writer of
//                  out[b,0, h*32 : h*32+32).
//   bids [64,148): ZERO blocks. grid-stride STG.256 zeros over rows 1..1023.

#define RED_BLOCKS   64
#define TOTAL_BLOCKS 148
#define ZERO_BLOCKS  (TOTAL_BLOCKS - RED_BLOCKS)
#define NTHREADS     1024

#define FLOATS_PER_BATCH 65536u   // 1024 rows * 64
#define F8_PER_BATCH     8192u    // 32B chunks per batch
#define F8_PER_ROW       8u
#define N_F8_TOTAL       (32u * F8_PER_BATCH)   // 262144

struct __align__(32) f8 { float a[8]; };

__device__ __forceinline__ void ldg256(f8& r, const float* p) {
    unsigned u0,u1,u2,u3,u4,u5,u6,u7;
    asm volatile("ld.global.v8.b32 {%0,%1,%2,%3,%4,%5,%6,%7}, [%8];"
        : "=r"(u0),"=r"(u1),"=r"(u2),"=r"(u3),
          "=r"(u4),"=r"(u5),"=r"(u6),"=r"(u7)
        : "l"(p));
    r.a[0]=__uint_as_float(u0); r.a[1]=__uint_as_float(u1);
    r.a[2]=__uint_as_float(u2); r.a[3]=__uint_as_float(u3);
    r.a[4]=__uint_as_float(u4); r.a[5]=__uint_as_float(u5);
    r.a[6]=__uint_as_float(u6); r.a[7]=__uint_as_float(u7);
}

__device__ __forceinline__ void stg256(float* p, const f8& v) {
    asm volatile("st.global.v8.b32 [%0], {%1,%2,%3,%4,%5,%6,%7,%8};"
        :: "l"(p),
           "r"(__float_as_uint(v.a[0])), "r"(__float_as_uint(v.a[1])),
           "r"(__float_as_uint(v.a[2])), "r"(__float_as_uint(v.a[3])),
           "r"(__float_as_uint(v.a[4])), "r"(__float_as_uint(v.a[5])),
           "r"(__float_as_uint(v.a[6])), "r"(__float_as_uint(v.a[7]))
        : "memory");
}

__device__ __forceinline__ void stg256_zero(float* p) {
    asm volatile("st.global.v8.b32 [%0], {%1,%1,%1,%1,%1,%1,%1,%1};"
        :: "l"(p), "r"(0u) : "memory");
}

__global__ void __launch_bounds__(NTHREADS, 1) um_fused_kernel(
    const float* __restrict__ x, float* __restrict__ out)
{
    const int bid = blockIdx.x;
    const int tid = threadIdx.x;

    if (bid < RED_BLOCKS) {
        // ---- READ block: (b, h) owns the 128B slice h of row 0 -----------
        const int b  = bid >> 1;
        const int h  = bid & 1;
        const int c  = tid & 3;        // 32B chunk within the 128B slice
        const int lg = tid >> 2;       // 0..255: row group

        const float* base = x + (size_t)b * FLOATS_PER_BATCH
                              + (size_t)lg * 64u + h * 32 + c * 8;

        // 4 batched LDG.256 (MLP=4 x 32B), rows lg + {0,256,512,768}
        f8 v0, v1, v2, v3;
        ldg256(v0, base);
        ldg256(v1, base + 256u * 64u);
        ldg256(v2, base + 512u * 64u);
        ldg256(v3, base + 768u * 64u);

        f8 s;
        #pragma unroll
        for (int k = 0; k < 8; ++k)
            s.a[k] = (v0.a[k] + v1.a[k]) + (v2.a[k] + v3.a[k]);

        // warp reduce: lanes sharing (lane & 3) share a chunk
        #pragma unroll
        for (int d = 16; d >= 4; d >>= 1)
            #pragma unroll
            for (int k = 0; k < 8; ++k)
                s.a[k] += __shfl_down_sync(0xffffffffu, s.a[k], d);

        __shared__ float sm[32][4][8];   // [warp][chunk][elem]
        const int lane = tid & 31;
        const int wid  = tid >> 5;
        if (lane < 4) {
            #pragma unroll
            for (int k = 0; k < 8; ++k) sm[wid][lane][k] = s.a[k];
        }
        __syncthreads();

        // single-warp final reduce: lane = (g, cc), g owns warps g*4..g*4+3
        if (wid == 0) {
            const int cc = lane & 3;
            const int g  = lane >> 2;    // 0..7
            float t[8];
            #pragma unroll
            for (int k = 0; k < 8; ++k)
                t[k] = (sm[g*4+0][cc][k] + sm[g*4+1][cc][k])
                     + (sm[g*4+2][cc][k] + sm[g*4+3][cc][k]);
            #pragma unroll
            for (int d = 16; d >= 4; d >>= 1)
                #pragma unroll
                for (int k = 0; k < 8; ++k)
                    t[k] += __shfl_down_sync(0xffffffffu, t[k], d);
            if (lane < 4) {
                f8 o;
                const float inv = 1.0f / 1024.0f;
                #pragma unroll
                for (int k = 0; k < 8; ++k) o.a[k] = t[k] * inv;
                stg256(out + (size_t)b * FLOATS_PER_BATCH + h * 32 + lane * 8, o);
            }
        }
    } else {
        // ---- ZERO block: everything except row 0 of each batch -----------
        const unsigned zid  = (unsigned)(bid - RED_BLOCKS);
        const unsigned step = ZERO_BLOCKS * (unsigned)NTHREADS;
        for (unsigned i = zid * (unsigned)NTHREADS + (unsigned)tid;
             i < N_F8_TOTAL; i += step) {
            if ((i & (F8_PER_BATCH - 1u)) >= F8_PER_ROW)   // skip row 0
                stg256_zero(out + (size_t)i * 8u);
        }
    }
}

extern "C" void kernel_launch(void* const* d_in, const int* in_sizes, int n_in,
                              void* d_out, int out_size) {
    const float* x = (const float*)d_in[0];   // user_embedding [32,1024,64]
    float* out = (float*)d_out;               // [32,1024,64]
    um_fused_kernel<<<TOTAL_BLOCKS, NTHREADS>>>(x, out);
}